// round 5
// baseline (speedup 1.0000x reference)
#include <cuda_runtime.h>
#include <cuda_bf16.h>

// Problem constants (fixed by the reference implementation)
#define DIM     128
#define C_MAX   10
#define K_NEG   5
#define NWORDS  (C_MAX + K_NEG)
#define MAXBLK  4096

// Scratch (no cudaMalloc allowed). g_count is zero at module load and is
// reset to 0 by the last finishing block each run -> deterministic under
// CUDA-graph replay.
__device__ double2       g_partial[MAXBLK];
__device__ unsigned int  g_count;

__device__ __forceinline__ float log_sigmoid(float x) {
    // Numerically stable: logsigmoid(x) = min(x,0) - log1p(exp(-|x|))
    return fminf(x, 0.0f) - log1pf(__expf(-fabsf(x)));
}

// NOTE: minBlocks=4 (NOT 8): 8 would cap regs at 32/thread and force
// sc[]/widx[] spills to local memory, destroying the batched-load MLP.
__global__ __launch_bounds__(256, 4)
void sg_fused_kernel(const int*   __restrict__ tgt,
                     const int*   __restrict__ ctx,
                     const int*   __restrict__ lens,
                     const int*   __restrict__ neg,
                     const float* __restrict__ in_emb,
                     const float* __restrict__ out_emb,
                     float*       __restrict__ out,
                     int batch)
{
    const int warp_global = (blockIdx.x * blockDim.x + threadIdx.x) >> 5;
    const int lane        = threadIdx.x & 31;
    const int warp_local  = threadIdx.x >> 5;

    __shared__ double s_pos[8];
    __shared__ double s_neg[8];
    __shared__ bool   s_is_last;

    double pos_per = 0.0, neg_per = 0.0;

    if (warp_global < batch) {
        const int b = warp_global;

        // ---- Phase 0: batch ALL index loads up front (scalar broadcasts) ----
        int widx[NWORDS];
        #pragma unroll
        for (int c = 0; c < C_MAX; ++c)
            widx[c] = __ldg(&ctx[b * C_MAX + c]);
        #pragma unroll
        for (int k = 0; k < K_NEG; ++k)
            widx[C_MAX + k] = __ldg(&neg[b * K_NEG + k]);
        const int t_idx = __ldg(&tgt[b]);
        const int len   = __ldg(&lens[b]);

        // ---- Phase 1: batch all 16 row gathers (4x LDG.128 lines per row/warp) ----
        // Target row: one float4 per lane (512B = 4 coalesced 128B lines).
        // __ldcs: streaming — cross-warp reuse lives in L2, not L1.
        const float4 t = __ldcs(((const float4*)(in_emb + (size_t)t_idx * DIM)) + lane);

        float sc[NWORDS];
        #pragma unroll
        for (int i = 0; i < NWORDS; ++i) {
            const float4 v = __ldcs(((const float4*)(out_emb + (size_t)widx[i] * DIM)) + lane);
            sc[i] = t.x * v.x + t.y * v.y + t.z * v.z + t.w * v.w;
        }

        // ---- Phase 2: butterfly-reduce all 15 dot products across the warp ----
        #pragma unroll
        for (int i = 0; i < NWORDS; ++i) {
            #pragma unroll
            for (int off = 16; off > 0; off >>= 1)
                sc[i] += __shfl_xor_sync(0xffffffffu, sc[i], off);
        }

        if (len > 0) {
            float ps = 0.0f;
            #pragma unroll
            for (int c = 0; c < C_MAX; ++c)
                if (c < len) ps += log_sigmoid(sc[c]);
            pos_per = -(double)ps / (double)len;

            float ns = 0.0f;
            #pragma unroll
            for (int k = 0; k < K_NEG; ++k)
                ns += log_sigmoid(-sc[C_MAX + k]);
            neg_per = -(double)ns / (double)K_NEG;
        }
    }

    // ---- Block-level partial sums ----
    if (lane == 0) {
        s_pos[warp_local] = pos_per;
        s_neg[warp_local] = neg_per;
    }
    __syncthreads();

    if (threadIdx.x == 0) {
        double p = 0.0, n = 0.0;
        #pragma unroll
        for (int i = 0; i < 8; ++i) { p += s_pos[i]; n += s_neg[i]; }
        g_partial[blockIdx.x] = make_double2(p, n);
        __threadfence();
        unsigned int old = atomicAdd(&g_count, 1u);
        s_is_last = (old == gridDim.x - 1);
    }
    __syncthreads();

    // ---- Last finishing block: reduce partials, write out, reset counter ----
    if (s_is_last) {
        __threadfence();  // acquire: make all g_partial writes visible
        const int nblk = gridDim.x;
        double p = 0.0, n = 0.0;
        for (int i = threadIdx.x; i < nblk; i += blockDim.x) {
            double2 v = g_partial[i];
            p += v.x; n += v.y;
        }
        #pragma unroll
        for (int off = 16; off > 0; off >>= 1) {
            p += __shfl_xor_sync(0xffffffffu, p, off);
            n += __shfl_xor_sync(0xffffffffu, n, off);
        }
        if (lane == 0) {
            s_pos[warp_local] = p;
            s_neg[warp_local] = n;
        }
        __syncthreads();
        if (threadIdx.x == 0) {
            double tp = 0.0, tn = 0.0;
            #pragma unroll
            for (int i = 0; i < 8; ++i) { tp += s_pos[i]; tn += s_neg[i]; }
            out[0] = (float)(tp / (double)batch);
            out[1] = (float)(tn / (double)batch);
            g_count = 0;  // restore state for next graph replay
        }
    }
}

extern "C" void kernel_launch(void* const* d_in, const int* in_sizes, int n_in,
                              void* d_out, int out_size)
{
    const int*   tgt     = (const int*)  d_in[0];  // (B,)
    const int*   ctx     = (const int*)  d_in[1];  // (B, C_MAX)
    const int*   lens    = (const int*)  d_in[2];  // (B,)
    const int*   neg     = (const int*)  d_in[3];  // (B, K_NEG)
    const float* in_emb  = (const float*)d_in[4];  // (VOCAB, DIM)
    const float* out_emb = (const float*)d_in[5];  // (VOCAB, DIM)
    float*       out     = (float*)d_out;

    const int batch   = in_sizes[0];               // 16384
    const int threads = 256;                       // 8 warps/block
    const int blocks  = (batch * 32 + threads - 1) / threads;  // 2048

    sg_fused_kernel<<<blocks, threads>>>(tgt, ctx, lens, neg, in_emb, out_emb, out, batch);
}

// round 6
// speedup vs baseline: 1.1635x; 1.1635x over previous
#include <cuda_runtime.h>
#include <cuda_bf16.h>

// Problem constants (fixed by the reference implementation)
#define DIM     128
#define C_MAX   10
#define K_NEG   5
#define NWORDS  (C_MAX + K_NEG)
#define MAXBLK  4096

// Scratch (no cudaMalloc allowed). g_count is zero at module load and is
// reset to 0 by the last finishing block each run -> deterministic under
// CUDA-graph replay.
__device__ double2       g_partial[MAXBLK];
__device__ unsigned int  g_count;

__device__ __forceinline__ float log_sigmoid(float x) {
    // logsigmoid(x) = min(x,0) - log(1 + exp(-|x|)); fast-math variants are
    // accurate to ~2ulp here (scores are tiny), far inside the 1e-3 budget.
    return fminf(x, 0.0f) - __logf(1.0f + __expf(-fabsf(x)));
}

// Merge step of the transposed multi-value warp reduction:
// A = partials of the value whose index-bit m is CLEAR, B = bit SET.
// Afterwards lanes with bit clear hold A (pair-summed), bit set hold B.
__device__ __forceinline__ float merge_pair(float A, float B, int m, int lane) {
    float send = (lane & m) ? A : B;
    float keep = (lane & m) ? B : A;
    return keep + __shfl_xor_sync(0xffffffffu, send, m);
}

// 100% occupancy target: 8 blocks x 256 thr -> 32 regs/thread. The chunked
// structure below keeps live state small enough to fit (evidence R5: for this
// latency-bound gather, occupancy >> per-warp MLP).
__global__ __launch_bounds__(256, 8)
void sg_fused_kernel(const int*   __restrict__ tgt,
                     const int*   __restrict__ ctx,
                     const int*   __restrict__ lens,
                     const int*   __restrict__ neg,
                     const float* __restrict__ in_emb,
                     const float* __restrict__ out_emb,
                     float*       __restrict__ out,
                     int batch)
{
    const unsigned F = 0xffffffffu;
    const int warp_global = (blockIdx.x * blockDim.x + threadIdx.x) >> 5;
    const int lane        = threadIdx.x & 31;
    const int warp_local  = threadIdx.x >> 5;

    __shared__ double s_pos[8];
    __shared__ double s_neg[8];
    __shared__ bool   s_is_last;

    double pos_per = 0.0, neg_per = 0.0;

    if (warp_global < batch) {
        const int b     = warp_global;
        const int len   = __ldg(&lens[b]);
        const int t_idx = __ldg(&tgt[b]);
        // Target row: one float4 per lane (512B = 4 coalesced 128B lines)
        const float4 t = __ldg(((const float4*)(in_emb + (size_t)t_idx * DIM)) + lane);

        // 16 virtual values: 0..9 = ctx scores, 10..14 = neg scores, 15 = pad.
        // Process in 4 chunks of 4; per chunk, fold the 4 per-lane partial dot
        // products down to ONE register via 3 shuffles (value idx bits 0..1).
        float acc[4];
        #pragma unroll
        for (int c = 0; c < 4; ++c) {
            float s[4];
            #pragma unroll
            for (int j = 0; j < 4; ++j) {
                const int v = c * 4 + j;
                if (v < NWORDS) {
                    const int w = (v < C_MAX) ? __ldg(&ctx[b * C_MAX + v])
                                              : __ldg(&neg[b * K_NEG + (v - C_MAX)]);
                    const float4 e = __ldg(((const float4*)(out_emb + (size_t)w * DIM)) + lane);
                    s[j] = t.x * e.x + t.y * e.y + t.z * e.z + t.w * e.w;
                } else {
                    s[j] = 0.0f;  // pad value 15
                }
            }
            float p01 = merge_pair(s[0], s[1], 1, lane);
            float p23 = merge_pair(s[2], s[3], 1, lane);
            acc[c]    = merge_pair(p01, p23, 2, lane);
        }
        // Fold chunks (value idx bits 2..3), then collapse lane-duplication.
        float q0 = merge_pair(acc[0], acc[1], 4, lane);
        float q1 = merge_pair(acc[2], acc[3], 4, lane);
        float r  = merge_pair(q0, q1, 8, lane);
        r += __shfl_xor_sync(F, r, 16);
        // Now lane i (and i+16) holds fully-reduced score (i & 15).

        // ONE logsigmoid per lane (was 15 per lane, x32 redundant).
        const float ls_p = log_sigmoid(r);
        const float ls_n = log_sigmoid(-r);
        float pc = (lane < len)                        ? ls_p : 0.0f;  // len <= 10
        float nc = (lane >= C_MAX && lane < NWORDS)    ? ls_n : 0.0f;
        #pragma unroll
        for (int off = 16; off > 0; off >>= 1) {
            pc += __shfl_xor_sync(F, pc, off);
            nc += __shfl_xor_sync(F, nc, off);
        }

        if (len > 0) {
            pos_per = -(double)pc / (double)len;
            neg_per = -(double)nc / (double)K_NEG;
        }
    }

    // ---- Block-level partial sums ----
    if (lane == 0) {
        s_pos[warp_local] = pos_per;
        s_neg[warp_local] = neg_per;
    }
    __syncthreads();

    if (threadIdx.x == 0) {
        double p = 0.0, n = 0.0;
        #pragma unroll
        for (int i = 0; i < 8; ++i) { p += s_pos[i]; n += s_neg[i]; }
        g_partial[blockIdx.x] = make_double2(p, n);
        __threadfence();
        unsigned int old = atomicAdd(&g_count, 1u);
        s_is_last = (old == gridDim.x - 1);
    }
    __syncthreads();

    // ---- Last finishing block: reduce partials, write out, reset counter ----
    if (s_is_last) {
        __threadfence();  // acquire: make all g_partial writes visible
        const int nblk = gridDim.x;
        double p = 0.0, n = 0.0;
        for (int i = threadIdx.x; i < nblk; i += blockDim.x) {
            double2 v = g_partial[i];
            p += v.x; n += v.y;
        }
        #pragma unroll
        for (int off = 16; off > 0; off >>= 1) {
            p += __shfl_xor_sync(F, p, off);
            n += __shfl_xor_sync(F, n, off);
        }
        if (lane == 0) {
            s_pos[warp_local] = p;
            s_neg[warp_local] = n;
        }
        __syncthreads();
        if (threadIdx.x == 0) {
            double tp = 0.0, tn = 0.0;
            #pragma unroll
            for (int i = 0; i < 8; ++i) { tp += s_pos[i]; tn += s_neg[i]; }
            out[0] = (float)(tp / (double)batch);
            out[1] = (float)(tn / (double)batch);
            g_count = 0;  // restore state for next graph replay
        }
    }
}

extern "C" void kernel_launch(void* const* d_in, const int* in_sizes, int n_in,
                              void* d_out, int out_size)
{
    const int*   tgt     = (const int*)  d_in[0];  // (B,)
    const int*   ctx     = (const int*)  d_in[1];  // (B, C_MAX)
    const int*   lens    = (const int*)  d_in[2];  // (B,)
    const int*   neg     = (const int*)  d_in[3];  // (B, K_NEG)
    const float* in_emb  = (const float*)d_in[4];  // (VOCAB, DIM)
    const float* out_emb = (const float*)d_in[5];  // (VOCAB, DIM)
    float*       out     = (float*)d_out;

    const int batch   = in_sizes[0];               // 16384
    const int threads = 256;                       // 8 warps/block
    const int blocks  = (batch * 32 + threads - 1) / threads;  // 2048

    sg_fused_kernel<<<blocks, threads>>>(tgt, ctx, lens, neg, in_emb, out_emb, out, batch);
}

// round 9
// speedup vs baseline: 1.1645x; 1.0009x over previous
#include <cuda_runtime.h>
#include <cuda_bf16.h>

// Problem constants (fixed by the reference implementation)
#define DIM     128
#define C_MAX   10
#define K_NEG   5
#define NWORDS  (C_MAX + K_NEG)
#define WPB     8           // warps (samples) per block
#define MAXBLK  4096

// Scratch (no cudaMalloc allowed). g_count is zero at module load and is
// reset to 0 by the last finishing block each run -> deterministic under
// CUDA-graph replay.
__device__ double2       g_partial[MAXBLK];
__device__ unsigned int  g_count;

__device__ __forceinline__ float log_sigmoid(float x) {
    // logsigmoid(x) = min(x,0) - log(1+exp(-|x|)); scores are tiny, fast-math
    // is ~2ulp here — far inside the 1e-3 budget (R6 passed at 9.4e-8).
    return fminf(x, 0.0f) - __logf(1.0f + __expf(-fabsf(x)));
}

// Transposed multi-value warp-reduce merge: A = value with index-bit m CLEAR,
// B = bit SET. After: lanes with bit clear hold pair-sum of A, set hold B.
__device__ __forceinline__ float merge_pair(float A, float B, int m, int lane) {
    float send = (lane & m) ? A : B;
    float keep = (lane & m) ? B : A;
    return keep + __shfl_xor_sync(0xffffffffu, send, m);
}

// (256,8): 32-reg cap, ~100% occupancy. sc[] spills are cheap STL/LDL
// (evidence R1 vs R6: full load batching >> avoiding spills).
__global__ __launch_bounds__(256, 8)
void sg_fused_kernel(const int*   __restrict__ tgt,
                     const int*   __restrict__ ctx,
                     const int*   __restrict__ lens,
                     const int*   __restrict__ neg,
                     const float* __restrict__ in_emb,
                     const float* __restrict__ out_emb,
                     float*       __restrict__ out,
                     int batch)
{
    const unsigned F = 0xffffffffu;
    const int lane       = threadIdx.x & 31;
    const int warp_local = threadIdx.x >> 5;
    const int b0         = blockIdx.x * WPB;           // first sample of block
    const int b          = b0 + warp_local;            // this warp's sample

    __shared__ int    s_ctx[WPB * C_MAX];              // 80 ints
    __shared__ int    s_neg[WPB * K_NEG];              // 40 ints
    __shared__ int    s_tgt[WPB];
    __shared__ int    s_len[WPB];
    __shared__ double s_pos[WPB];
    __shared__ double s_neg_acc[WPB];
    __shared__ bool   s_is_last;

    // ---- Stage all block indices via coalesced loads (contiguous in GMEM).
    // Disjoint tid ranges: ctx [0,80), neg [96,136), tgt [160,168), len [192,200).
    {
        const int tid   = threadIdx.x;
        const int nrem  = batch - b0;
        const int nctx  = min(WPB * C_MAX, nrem * C_MAX);
        const int nneg  = min(WPB * K_NEG, nrem * K_NEG);
        const int nsamp = min(WPB, nrem);
        if (tid < nctx)                               s_ctx[tid] = ctx[b0 * C_MAX + tid];
        const int jn = tid - 96;
        if (jn >= 0 && jn < nneg)                     s_neg[jn]  = neg[b0 * K_NEG + jn];
        const int jt = tid - 160;
        if (jt >= 0 && jt < nsamp)                    s_tgt[jt]  = tgt[b0 + jt];
        const int jl = tid - 192;
        if (jl >= 0 && jl < nsamp)                    s_len[jl]  = lens[b0 + jl];
    }
    __syncthreads();

    double pos_per = 0.0, neg_per = 0.0;

    if (b < batch) {
        const int len = s_len[warp_local];

        // ---- Fully-batched gather: 16 rows, FFMA into sc[] per row.
        // All 16 LDG.128 front-batch (MLP ~16); index reads are 29-cyc LDS.
        const float4 t = __ldg(((const float4*)(in_emb
                              + (size_t)s_tgt[warp_local] * DIM)) + lane);

        float sc[16];
        #pragma unroll
        for (int i = 0; i < NWORDS; ++i) {
            const int w = (i < C_MAX) ? s_ctx[warp_local * C_MAX + i]
                                      : s_neg[warp_local * K_NEG + (i - C_MAX)];
            const float4 e = __ldg(((const float4*)(out_emb + (size_t)w * DIM)) + lane);
            sc[i] = t.x * e.x + t.y * e.y + t.z * e.z + t.w * e.w;
        }
        sc[15] = 0.0f;  // pad

        // ---- Transposed merge tree AFTER all loads: 15 merges + 1 shuffle.
        float m1[8];
        #pragma unroll
        for (int i = 0; i < 8; ++i) m1[i] = merge_pair(sc[2*i], sc[2*i+1], 1, lane);
        float m2[4];
        #pragma unroll
        for (int i = 0; i < 4; ++i) m2[i] = merge_pair(m1[2*i], m1[2*i+1], 2, lane);
        float m4_0 = merge_pair(m2[0], m2[1], 4, lane);
        float m4_1 = merge_pair(m2[2], m2[3], 4, lane);
        float r    = merge_pair(m4_0, m4_1, 8, lane);
        r += __shfl_xor_sync(F, r, 16);
        // lane i (and i+16) now holds fully-reduced score (i & 15).

        // ---- ONE logsigmoid per lane; masked contribution sums.
        const float ls_p = log_sigmoid(r);
        const float ls_n = log_sigmoid(-r);
        float pc = (lane < len)                     ? ls_p : 0.0f;   // len <= 10
        float nc = (lane >= C_MAX && lane < NWORDS) ? ls_n : 0.0f;
        #pragma unroll
        for (int off = 16; off > 0; off >>= 1) {
            pc += __shfl_xor_sync(F, pc, off);
            nc += __shfl_xor_sync(F, nc, off);
        }

        if (len > 0) {
            pos_per = -(double)pc / (double)len;
            neg_per = -(double)nc / (double)K_NEG;
        }
    }

    // ---- Block-level partial sums ----
    if (lane == 0) {
        s_pos[warp_local]     = pos_per;
        s_neg_acc[warp_local] = neg_per;
    }
    __syncthreads();

    if (threadIdx.x == 0) {
        double p = 0.0, n = 0.0;
        #pragma unroll
        for (int i = 0; i < WPB; ++i) { p += s_pos[i]; n += s_neg_acc[i]; }
        g_partial[blockIdx.x] = make_double2(p, n);
        __threadfence();
        unsigned int old = atomicAdd(&g_count, 1u);
        s_is_last = (old == gridDim.x - 1);
    }
    __syncthreads();

    // ---- Last finishing block: reduce partials, write out, reset counter ----
    if (s_is_last) {
        __threadfence();  // acquire: make all g_partial writes visible
        const int nblk = gridDim.x;
        double p = 0.0, n = 0.0;
        for (int i = threadIdx.x; i < nblk; i += blockDim.x) {
            double2 v = g_partial[i];
            p += v.x; n += v.y;
        }
        #pragma unroll
        for (int off = 16; off > 0; off >>= 1) {
            p += __shfl_xor_sync(F, p, off);
            n += __shfl_xor_sync(F, n, off);
        }
        if (lane == 0) {
            s_pos[warp_local]     = p;
            s_neg_acc[warp_local] = n;
        }
        __syncthreads();
        if (threadIdx.x == 0) {
            double tp = 0.0, tn = 0.0;
            #pragma unroll
            for (int i = 0; i < WPB; ++i) { tp += s_pos[i]; tn += s_neg_acc[i]; }
            out[0] = (float)(tp / (double)batch);
            out[1] = (float)(tn / (double)batch);
            g_count = 0;  // restore state for next graph replay
        }
    }
}

extern "C" void kernel_launch(void* const* d_in, const int* in_sizes, int n_in,
                              void* d_out, int out_size)
{
    const int*   tgt     = (const int*)  d_in[0];  // (B,)
    const int*   ctx     = (const int*)  d_in[1];  // (B, C_MAX)
    const int*   lens    = (const int*)  d_in[2];  // (B,)
    const int*   neg     = (const int*)  d_in[3];  // (B, K_NEG)
    const float* in_emb  = (const float*)d_in[4];  // (VOCAB, DIM)
    const float* out_emb = (const float*)d_in[5];  // (VOCAB, DIM)
    float*       out     = (float*)d_out;

    const int batch   = in_sizes[0];               // 16384
    const int threads = 32 * WPB;                  // 256
    const int blocks  = (batch + WPB - 1) / WPB;   // 2048

    sg_fused_kernel<<<blocks, threads>>>(tgt, ctx, lens, neg, in_emb, out_emb, out, batch);
}